// round 7
// baseline (speedup 1.0000x reference)
#include <cuda_runtime.h>

// Problem constants (fixed by the reference):
// B=16, W=256, S=512, F=768, L=4, E=256, V=50000
#define BB 16
#define WW 256
#define SS 512
#define LL 4
#define NW (WW - 1)

// float4 strides inside layers[L, B, S, F/4=192]
#define LSTRIDE (BB * SS * 192)   // 1,572,864
#define BSTRIDE (SS * 192)        //    98,304

// Streaming load: non-coherent, promote L2 fill granularity to 256B.
__device__ __forceinline__ float4 ldg_stream(const float4* p) {
    float4 v;
    asm("ld.global.nc.L2::256B.v4.f32 {%0,%1,%2,%3}, [%4];"
        : "=f"(v.x), "=f"(v.y), "=f"(v.z), "=f"(v.w)
        : "l"(p));
    return v;
}

// Generic (slow) path: arbitrary span. Only taken if the speculation
// (ss == 2w-1, len == 2) misses — never with this dataset, kept for
// correctness on arbitrary inputs.
__device__ __noinline__ float4 span_mix_generic(
    const float4* __restrict__ layers4, int b, int ss, int se, int t,
    float w0, float w1, float w2, float w3, float g)
{
    float4 acc = make_float4(0.f, 0.f, 0.f, 0.f);
    const int len = se - ss;
    if (len <= 0) return acc;
    for (int s = ss; s < se; s++) {
        const float4* p = layers4 + (size_t)b * BSTRIDE + (size_t)s * 192 + t;
        float4 v0 = p[0 * LSTRIDE];
        float4 v1 = p[1 * LSTRIDE];
        float4 v2 = p[2 * LSTRIDE];
        float4 v3 = p[3 * LSTRIDE];
        acc.x += w0*v0.x + w1*v1.x + w2*v2.x + w3*v3.x;
        acc.y += w0*v0.y + w1*v1.y + w2*v2.y + w3*v3.y;
        acc.z += w0*v0.z + w1*v1.z + w2*v2.z + w3*v3.z;
        acc.w += w0*v0.w + w1*v1.w + w2*v2.w + w3*v3.w;
    }
    const float sc = g / (float)len;
    acc.x *= sc; acc.y *= sc; acc.z *= sc; acc.w *= sc;
    return acc;
}

// Grid: one block per (b, w) pair = 4096 blocks, 192 threads.
// KEY IDEA: the 8 streaming layer loads are issued at a SPECULATED span
// address ss_g = 2w-1 (pure function of blockIdx, no memory dependency),
// concurrently with the actual span-index loads. On return we verify the
// speculation; hit -> combine (100% of this dataset), miss -> generic path.
// This removes the serial index->data round-trip from every CTA's critical
// path, which is what capped DRAM utilization at ~67%.
__global__ __launch_bounds__(192, 5)
void bert_lexer_fused(
    const int* __restrict__ word_indices,   // [B, W]
    const int* __restrict__ span_starts,    // [B, W-1]
    const int* __restrict__ span_ends,      // [B, W-1]
    const float4* __restrict__ emb4,        // [V, E/4=64]
    const float4* __restrict__ layers4,     // [L, B, S, F/4=192]
    const float* __restrict__ layer_weights,// [L]
    const float* __restrict__ gamma,        // [1]
    float4* __restrict__ out4)              // [B, W, (E+F)/4=256]
{
    const int bw = blockIdx.x;        // b*W + w
    const int b  = bw >> 8;           // W = 256
    const int w  = bw & (WW - 1);
    const int t  = threadIdx.x;       // 0..191 -> float4 index within F

    float4* __restrict__ outrow = out4 + (size_t)bw * 256;
    const bool do_emb = (t < 64);

    // ---- SPECULATIVE streaming loads: no memory dependency in front ----
    // ss_g = 2w-1 in [1, 509]; ss_g+1 <= 510 < S=512 -> always in bounds.
    float4 a0, b0, a1, b1, a2, b2, a3, b3;
    const int ss_g = (w << 1) - 1;
    if (w > 0) {
        const float4* base = layers4 + (size_t)b * BSTRIDE + (size_t)ss_g * 192 + t;
        a0 = ldg_stream(base + 0 * LSTRIDE      );
        b0 = ldg_stream(base + 0 * LSTRIDE + 192);
        a1 = ldg_stream(base + 1 * LSTRIDE      );
        b1 = ldg_stream(base + 1 * LSTRIDE + 192);
        a2 = ldg_stream(base + 2 * LSTRIDE      );
        b2 = ldg_stream(base + 2 * LSTRIDE + 192);
        a3 = ldg_stream(base + 3 * LSTRIDE      );
        b3 = ldg_stream(base + 3 * LSTRIDE + 192);
    }

    // ---- concurrent: actual span indices, word index, embedding row ----
    int ss = 0, se = 0;
    if (w > 0) {
        const int si = b * NW + (w - 1);
        ss = __ldg(span_starts + si);
        se = __ldg(span_ends   + si);
    }
    const int idx = __ldg(word_indices + bw);
    float4 ev = make_float4(0.f, 0.f, 0.f, 0.f);
    if (do_emb) ev = ldg_stream(emb4 + (size_t)idx * 64 + t);

    // ---- softmax over 4 layer weights (cached scalar loads) ----
    const float lw0 = __ldg(layer_weights + 0), lw1 = __ldg(layer_weights + 1);
    const float lw2 = __ldg(layer_weights + 2), lw3 = __ldg(layer_weights + 3);
    const float g   = __ldg(gamma);
    const float mx  = fmaxf(fmaxf(lw0, lw1), fmaxf(lw2, lw3));
    const float e0  = __expf(lw0 - mx), e1 = __expf(lw1 - mx);
    const float e2  = __expf(lw2 - mx), e3 = __expf(lw3 - mx);
    const float inv = 1.0f / (e0 + e1 + e2 + e3);
    const float sw0 = e0 * inv, sw1 = e1 * inv, sw2 = e2 * inv, sw3 = e3 * inv;

    // ---- verify speculation and combine ----
    float4 acc = make_float4(0.f, 0.f, 0.f, 0.f);
    if (w > 0) {
        if (ss == ss_g && se == ss_g + 2) {
            const float sc = g * 0.5f;
            const float h0 = sw0 * sc, h1 = sw1 * sc, h2 = sw2 * sc, h3 = sw3 * sc;
            acc.x = h0*(a0.x+b0.x) + h1*(a1.x+b1.x) + h2*(a2.x+b2.x) + h3*(a3.x+b3.x);
            acc.y = h0*(a0.y+b0.y) + h1*(a1.y+b1.y) + h2*(a2.y+b2.y) + h3*(a3.y+b3.y);
            acc.z = h0*(a0.z+b0.z) + h1*(a1.z+b1.z) + h2*(a2.z+b2.z) + h3*(a3.z+b3.z);
            acc.w = h0*(a0.w+b0.w) + h1*(a1.w+b1.w) + h2*(a2.w+b2.w) + h3*(a3.w+b3.w);
        } else {
            acc = span_mix_generic(layers4, b, ss, se, t, sw0, sw1, sw2, sw3, g);
        }
    }

    // Evict-first streaming stores: output has no reuse, keep L2 for layers.
    if (do_emb) __stcs(outrow + t, ev);
    __stcs(outrow + 64 + t, acc);   // w==0 or empty span -> zeros (reference)
}

extern "C" void kernel_launch(void* const* d_in, const int* in_sizes, int n_in,
                              void* d_out, int out_size)
{
    const int*    word_indices  = (const int*)   d_in[0];
    const int*    span_starts   = (const int*)   d_in[1];
    const int*    span_ends     = (const int*)   d_in[2];
    const float4* emb4          = (const float4*)d_in[3];
    const float4* layers4       = (const float4*)d_in[4];
    const float*  layer_weights = (const float*) d_in[5];
    const float*  gamma         = (const float*) d_in[6];
    float4*       out4          = (float4*)      d_out;

    (void)in_sizes; (void)n_in; (void)out_size;

    bert_lexer_fused<<<BB * WW, 192>>>(word_indices, span_starts, span_ends,
                                       emb4, layers4, layer_weights, gamma, out4);
}